// round 14
// baseline (speedup 1.0000x reference)
#include <cuda_runtime.h>
#include <cuda_bf16.h>
#include <mma.h>
#include <math.h>
#include <float.h>

using namespace nvcuda;

// ---------------- problem constants ----------------
#define BB 2048
#define TT 200
#define KK 128
#define UD 128
#define D1 80
#define D2 40
#define DJ 384
#define TH 104                   // max t per half-CTA (balanced split <= 100)
#define ALD2 136                 // A/B1 ldm: 272B rows (16 mod 128 -> conflict-free)
#define S1LD 88                  // 176B (48 mod 128)
#define D1LD 88                  // 352B (96 mod 128)
#define D2LD 56                  // 224B (96 mod 128)
#define BN_EPS 1e-3f
#define RSQRT_K 0.08838834764831843f

// ---- ATT-A SMEM layout (bytes) per half-CTA ----
#define A_OFF    0
#define B1S_OFF  30464
#define S1_OFF   52224
#define B2S_OFF  71936
#define MISC_OFF 80384
#define SMEM_ATT_TOTAL 81536

// ---------------- scratch (device globals) ----------
__device__ float g_q[BB * KK];
__device__ float g_cq[BB * D1];
__device__ float g_Wac[KK * D1];
__device__ uint2 g_B1pk[D1 * 64];            // [j][kp]: {bf16x2 Wbc, bf16x2 W1d}
__device__ __nv_bfloat16 g_B2bf[48 * D1];    // [n][k] W2^T padded to 48 n
__device__ float g_attn[BB * 224];           // raw scores (t<len only)
__device__ float g_obias[BB];
__device__ float g_hist_attn[BB * KK];
__device__ float g_join[BB * DJ];
__device__ float g_y1[BB * D1];
__device__ float g_y2[BB * D2];
__device__ float g_m1[KK],  g_r1[KK];
__device__ float g_m2[DJ],  g_r2[DJ];
__device__ float g_m3[D1],  g_r3[D1];
__device__ float g_m4[D2],  g_r4[D2];

// ---------------- helpers ----------------
__device__ __forceinline__ unsigned long long pack2(float x, float y) {
    unsigned long long r;
    asm("mov.b64 %0, {%1, %2};" : "=l"(r) : "f"(x), "f"(y));
    return r;
}
__device__ __forceinline__ float2 unpack2(unsigned long long v) {
    float2 r;
    asm("mov.b64 {%0, %1}, %2;" : "=f"(r.x), "=f"(r.y) : "l"(v));
    return r;
}
__device__ __forceinline__ void fma2(unsigned long long& d, unsigned long long a,
                                     unsigned long long b) {
    asm("fma.rn.f32x2 %0, %1, %2, %0;" : "+l"(d) : "l"(a), "l"(b));
}
__device__ __forceinline__ float sigf(float x) {
    float t;
    asm("tanh.approx.f32 %0, %1;" : "=f"(t) : "f"(x * 0.5f));
    return fmaf(0.5f, t, 0.5f);
}
__device__ __forceinline__ float sigf_precise(float x) {
    return __fdividef(1.0f, 1.0f + __expf(-x));
}
__device__ __forceinline__ unsigned int bf16x2_of(float x, float y) {
    unsigned int r;
    asm("cvt.rn.bf16x2.f32 %0, %2, %1;" : "=r"(r) : "f"(x), "f"(y));
    return r;
}

// =====================================================================
// fold: g_Wac [k][n] + packed bf16 B1 pairs + bf16 B2 [48][80]
// =====================================================================
__global__ void fold_W(const float* __restrict__ W1, const float* __restrict__ W2) {
    int i = blockIdx.x * blockDim.x + threadIdx.x;
    if (i < KK * D1) {
        int k = i / D1, n = i - k * D1;
        g_Wac[i] = W1[(size_t)k * D1 + n] + W1[(size_t)(2 * KK + k) * D1 + n];
    }
    if (i < D1 * 64) {
        int j = i >> 6, k = (i & 63) << 1;
        float wbc0 = W1[(size_t)(KK + k) * D1 + j]     - W1[(size_t)(2 * KK + k) * D1 + j];
        float wbc1 = W1[(size_t)(KK + k + 1) * D1 + j] - W1[(size_t)(2 * KK + k + 1) * D1 + j];
        float w1d0 = W1[(size_t)(3 * KK + k) * D1 + j];
        float w1d1 = W1[(size_t)(3 * KK + k + 1) * D1 + j];
        g_B1pk[i] = make_uint2(bf16x2_of(wbc0, wbc1), bf16x2_of(w1d0, w1d1));
    }
    if (i < 48 * D1) {
        int n = i / D1, k = i - n * D1;
        g_B2bf[i] = (n < D2) ? __float2bfloat16(W2[(size_t)k * D2 + n])
                             : __float2bfloat16(0.0f);
    }
}

__global__ void prep_batch(const int* __restrict__ user, const int* __restrict__ item,
                           const int* __restrict__ cate_list,
                           const float* __restrict__ user_table,
                           const float* __restrict__ item_table,
                           const float* __restrict__ cate_table,
                           const float* __restrict__ item_bias) {
    int b = blockIdx.x, tid = threadIdx.x;
    int it = item[b];
    float qv = (tid < 64) ? item_table[(size_t)it * 64 + tid]
                          : cate_table[(size_t)cate_list[it] * 64 + (tid - 64)];
    g_q[b * KK + tid] = qv;
    g_join[b * DJ + UD + tid] = qv;
    g_join[b * DJ + tid] = user_table[(size_t)user[b] * UD + tid];
    if (tid == 0) g_obias[b] = item_bias[it];
}

// =====================================================================
// SMEM-staged tail GEMM (proven R4)
// =====================================================================
template<int KIN, int JOUT, int MODE>
__global__ __launch_bounds__(256) void gemm_smemW(
    const float* __restrict__ in, int in_stride,
    const float* __restrict__ W, const float* __restrict__ bias,
    float* __restrict__ out, int out_stride, int out_off,
    const float* __restrict__ mean, const float* __restrict__ rstd,
    const float* __restrict__ p1, const float* __restrict__ p2)
{
    constexpr int KP  = KIN + 2;
    constexpr int NR  = 256 / JOUT;
    constexpr int ACT = NR * JOUT;
    constexpr int M   = (16 + NR - 1) / NR;
    extern __shared__ float smg[];
    float* ws = smg;
    float* xs = ws + JOUT * KP;
    const int b0 = blockIdx.x * 16;

    for (int i = threadIdx.x; i < KIN * JOUT; i += 256) {
        int k = i / JOUT, j = i - k * JOUT;
        ws[j * KP + k] = W[i];
    }
    for (int i = threadIdx.x; i < 16 * KIN; i += 256) {
        int r = i / KIN, k = i - r * KIN;
        float v = in[(size_t)(b0 + r) * in_stride + k];
        if constexpr (MODE == 1) {
            v = (v - mean[k]) * rstd[k] * p1[k] + p2[k];
        } else if constexpr (MODE == 2) {
            float xn = (v - mean[k]) * rstd[k];
            float pp = sigf(p2[k] * xn);
            v = v * (pp + p1[k] * (1.0f - pp));
        }
        xs[r * KP + k] = v;
    }
    __syncthreads();

    if (threadIdx.x < ACT) {
        const int j  = threadIdx.x % JOUT;
        const int rg = threadIdx.x / JOUT;
        const float bj = bias[j];
        unsigned long long acc[M];
        const unsigned long long* xpr[M];
#pragma unroll
        for (int m = 0; m < M; m++) {
            acc[m] = 0ULL;
            xpr[m] = (const unsigned long long*)(xs + (rg + NR * m) * KP);
        }
        const unsigned long long* wp = (const unsigned long long*)(ws + j * KP);
#pragma unroll 4
        for (int kp = 0; kp < KIN / 2; kp++) {
            unsigned long long w2 = wp[kp];
#pragma unroll
            for (int m = 0; m < M; m++)
                fma2(acc[m], xpr[m][kp], w2);
        }
#pragma unroll
        for (int m = 0; m < M; m++) {
            int r = rg + NR * m;
            if (r < 16) {
                float2 v = unpack2(acc[m]);
                out[(size_t)(b0 + r) * out_stride + out_off + j] = v.x + v.y + bj;
            }
        }
    }
}

__global__ void colstats2(const float* __restrict__ x, int rows, int cols,
                          float* __restrict__ mean, float* __restrict__ rstd)
{
    __shared__ float ss[16][33], sq[16][33];
    int tx = threadIdx.x & 31, ty = threadIdx.x >> 5;
    int col = blockIdx.x * 32 + tx;
    float s = 0.f, q = 0.f;
    if (col < cols) {
#pragma unroll 8
        for (int r = ty; r < rows; r += 16) {
            float v = x[(size_t)r * cols + col];
            s += v; q = fmaf(v, v, q);
        }
    }
    ss[ty][tx] = s; sq[ty][tx] = q;
    __syncthreads();
    if (ty == 0 && col < cols) {
        float S = 0.f, Q = 0.f;
#pragma unroll
        for (int i = 0; i < 16; i++) { S += ss[i][tx]; Q += sq[i][tx]; }
        float m = S / (float)rows;
        float v = Q / (float)rows - m * m;
        mean[col] = m;
        rstd[col] = rsqrtf(v + BN_EPS);
    }
}

// =====================================================================
// ATT-A: balanced half-batch per CTA. bf16 wmma, HFMA2 weff build.
// grid = 2*BB, 256 threads, 81.5KB smem -> 2 CTAs/SM.
// Writes ONLY real scores (t < len); ATT-B applies the mask.
// =====================================================================
__global__ __launch_bounds__(256, 2) void att_kernel(
    const int* __restrict__ history, const int* __restrict__ length,
    const int* __restrict__ cate_list,
    const float* __restrict__ item_table, const float* __restrict__ cate_table,
    const float* __restrict__ b2, const float* __restrict__ W3,
    const float* __restrict__ b3)
{
    extern __shared__ __align__(16) char smc[];
    __nv_bfloat16* a_bf = (__nv_bfloat16*)(smc + A_OFF);    // [112][136]
    float*         d1f  = (float*)(smc + A_OFF);            // overlay [112][88]
    float*         d2f  = (float*)(smc + A_OFF);            // overlay [112][56]
    __nv_bfloat16* b1s  = (__nv_bfloat16*)(smc + B1S_OFF);  // weff [80][136]
    __nv_bfloat16* s1p  = (__nv_bfloat16*)(smc + S1_OFF);   // [112][88]
    __nv_bfloat16* b2s  = (__nv_bfloat16*)(smc + B2S_OFF);  // [48][88]
    unsigned int* qpk = (unsigned int*)(smc + MISC_OFF);    // 64 bf16x2
    float* cqs = (float*)(qpk + 64);                        // 80
    float* w3s = cqs + 80;                                  // 40
    float* b2v = w3s + 40;                                  // 40

    const int bx  = blockIdx.x;
    const int b   = bx >> 1;
    const int len = length[b];
    const int lh  = (len + 1) >> 1;                 // balanced split point
    const int h0  = (bx & 1) ? lh : 0;
    const int lenc = (bx & 1) ? (len - lh) : lh;    // rows this CTA computes
    const int tid = threadIdx.x;
    const int wid = tid >> 5;

    if (lenc <= 0) return;                          // nothing to do (len==1, CTA1)
    const int MT = (lenc + 15) >> 4;                // active m-tiles (1..7)

    // ---- stage small params ----
    if (tid < 64) {
        float2 qv = *(const float2*)(g_q + b * KK + 2 * tid);
        qpk[tid] = bf16x2_of(qv.x, qv.y);
    }
    if (tid < D1) cqs[tid] = g_cq[b * D1 + tid];
    if (tid < D2) { w3s[tid] = W3[tid]; b2v[tid] = b2[tid]; }

    // zero only tail rows [lenc, MT*16), k<128 (16 uint4 per row)
    {
        uint4 z = make_uint4(0, 0, 0, 0);
        int nrows = MT * 16 - lenc;                 // 0..15
        for (int i = tid; i < nrows * 16; i += 256) {
            int r = lenc + i / 16, c = (i & 15) << 3;
            *(uint4*)(a_bf + r * ALD2 + c) = z;
        }
    }
    // stage B2 (80 -> 88 restride)
    for (int i = tid; i < 48 * 10; i += 256) {
        int n = i / 10, c8 = (i % 10) << 3;
        *(uint4*)(b2s + n * S1LD + c8) = *(const uint4*)(g_B2bf + n * D1 + c8);
    }
    __syncthreads();   // qpk ready before weff build

    // ---- weff build: one LDG.64 + HFMA2 + STS.32 per (j, k-pair) ----
    for (int i = tid; i < D1 * 64; i += 256) {      // 20 iterations
        int j = i >> 6, kp2 = i & 63;
        uint2 w = g_B1pk[i];
        __nv_bfloat162 wbc = *reinterpret_cast<__nv_bfloat162*>(&w.x);
        __nv_bfloat162 w1d = *reinterpret_cast<__nv_bfloat162*>(&w.y);
        __nv_bfloat162 qq  = *reinterpret_cast<__nv_bfloat162*>(&qpk[kp2]);
        __nv_bfloat162 r   = __hfma2(qq, w1d, wbc);
        *(__nv_bfloat162*)(b1s + j * ALD2 + 2 * kp2) = r;
    }

    // ---- gather A = hist rows (t local, only t < lenc) ----
    {
        int t = tid >> 1, half = tid & 1;
        if (t < lenc) {
            int hidx = history[b * TT + h0 + t];
            const float4* row = half
                ? (const float4*)(cate_table + (size_t)cate_list[hidx] * 64)
                : (const float4*)(item_table + (size_t)hidx * 64);
            int kb0 = half * 64;
            __nv_bfloat16* arow = a_bf + t * ALD2;
#pragma unroll
            for (int c = 0; c < 16; c++) {
                float4 v = row[c];
                int k = kb0 + 4 * c;
                *(unsigned int*)(arow + k)     = bf16x2_of(v.x, v.y);
                *(unsigned int*)(arow + k + 2) = bf16x2_of(v.z, v.w);
            }
        }
    }
    __syncthreads();

    // ---- layer 1: D1[MT*16 x 80] = A @ weff^T (warp == m-tile) ----
    wmma::fragment<wmma::accumulator, 16, 16, 16, float> acc1[5];
    if (wid < MT) {
#pragma unroll
        for (int nt = 0; nt < 5; nt++) wmma::fill_fragment(acc1[nt], 0.0f);
#pragma unroll
        for (int ks = 0; ks < 8; ks++) {
            wmma::fragment<wmma::matrix_a, 16, 16, 16, __nv_bfloat16, wmma::row_major> af;
            wmma::load_matrix_sync(af, a_bf + wid * 16 * ALD2 + ks * 16, ALD2);
#pragma unroll
            for (int nt = 0; nt < 5; nt++) {
                wmma::fragment<wmma::matrix_b, 16, 16, 16, __nv_bfloat16, wmma::col_major> bf;
                wmma::load_matrix_sync(bf, b1s + nt * 16 * ALD2 + ks * 16, ALD2);
                wmma::mma_sync(acc1[nt], af, bf, acc1[nt]);
            }
        }
    }
    __syncthreads();   // A + B1 dead; accumulators in regs
    if (wid < MT) {
#pragma unroll
        for (int nt = 0; nt < 5; nt++)
            wmma::store_matrix_sync(d1f + wid * 16 * D1LD + nt * 16, acc1[nt], D1LD,
                                    wmma::mem_row_major);
    }
    __syncthreads();

    // ---- epilogue 1: S1 = sigf(D1 + cq) bf16 ----
    {
        int t = tid >> 1, half = tid & 1;
        if (t < MT * 16) {
            const float* dr = d1f + t * D1LD + half * 40;
            __nv_bfloat16* sr = s1p + t * S1LD + half * 40;
            const float* cq = cqs + half * 40;
#pragma unroll
            for (int jp = 0; jp < 20; jp++) {
                float v0 = sigf(dr[2 * jp]     + cq[2 * jp]);
                float v1 = sigf(dr[2 * jp + 1] + cq[2 * jp + 1]);
                *(unsigned int*)(sr + 2 * jp) = bf16x2_of(v0, v1);
            }
        }
    }
    __syncthreads();

    // ---- layer 2: D2[MT*16 x 48] = S1 @ B2^T ----
    for (int idx = wid; idx < MT * 3; idx += 8) {
        int mt = idx / 3, nt = idx - 3 * mt;
        wmma::fragment<wmma::accumulator, 16, 16, 16, float> acc2;
        wmma::fill_fragment(acc2, 0.0f);
#pragma unroll
        for (int ks = 0; ks < 5; ks++) {
            wmma::fragment<wmma::matrix_a, 16, 16, 16, __nv_bfloat16, wmma::row_major> af;
            wmma::fragment<wmma::matrix_b, 16, 16, 16, __nv_bfloat16, wmma::col_major> bf;
            wmma::load_matrix_sync(af, s1p + mt * 16 * S1LD + ks * 16, S1LD);
            wmma::load_matrix_sync(bf, b2s + nt * 16 * S1LD + ks * 16, S1LD);
            wmma::mma_sync(acc2, af, bf, acc2);
        }
        wmma::store_matrix_sync(d2f + mt * 16 * D2LD + nt * 16, acc2, D2LD,
                                wmma::mem_row_major);
    }
    __syncthreads();

    // ---- layer 3: real scores only ----
    if (tid < lenc) {
        float score = b3[0];
        const float* dr = d2f + tid * D2LD;
#pragma unroll
        for (int n = 0; n < D2; n++)
            score = fmaf(sigf(dr[n] + b2v[n]), w3s[n], score);
        g_attn[b * 224 + h0 + tid] = score * RSQRT_K;
    }
}

// =====================================================================
// ATT-B: masked softmax + exact fp32 weighted embedding bag
// =====================================================================
__global__ __launch_bounds__(256) void attnbag_kernel(
    const int* __restrict__ history, const int* __restrict__ length,
    const int* __restrict__ cate_list,
    const float* __restrict__ item_table, const float* __restrict__ cate_table)
{
    __shared__ float part[8][128];
    __shared__ float red[256];
    __shared__ float attn_s[224];
    const int b = blockIdx.x;
    const int tid = threadIdx.x;
    const int lane = tid & 31, w = tid >> 5;
    const int len = length[b];

    float sc = (tid < len) ? g_attn[b * 224 + tid] : -FLT_MAX;
    red[tid] = sc;
    __syncthreads();
#pragma unroll
    for (int s = 128; s > 0; s >>= 1) {
        if (tid < s) red[tid] = fmaxf(red[tid], red[tid + s]);
        __syncthreads();
    }
    const float mx = red[0];
    __syncthreads();
    float p = (tid < len) ? __expf(sc - mx) : 0.0f;
    red[tid] = p;
    __syncthreads();
#pragma unroll
    for (int s = 128; s > 0; s >>= 1) {
        if (tid < s) red[tid] += red[tid + s];
        __syncthreads();
    }
    const float inv = 1.0f / red[0];
    if (tid < 224) attn_s[tid] = (tid < len) ? p * inv : 0.0f;
    __syncthreads();

    float4 acc = make_float4(0.f, 0.f, 0.f, 0.f);
    for (int t = w; t < len; t += 8) {
        float a = attn_s[t];
        int hidx = history[b * TT + t];
        const float4* row = (lane < 16)
            ? (const float4*)(item_table + (size_t)hidx * 64) + lane
            : (const float4*)(cate_table + (size_t)cate_list[hidx] * 64) + (lane - 16);
        float4 v = *row;
        acc.x = fmaf(a, v.x, acc.x);
        acc.y = fmaf(a, v.y, acc.y);
        acc.z = fmaf(a, v.z, acc.z);
        acc.w = fmaf(a, v.w, acc.w);
    }
    ((float4*)part[w])[lane] = acc;
    __syncthreads();
    if (tid < 128) {
        float s = 0.f;
#pragma unroll
        for (int i = 0; i < 8; i++) s += part[i][tid];
        g_hist_attn[b * KK + tid] = s;
    }
}

// =====================================================================
// final: dice + fc3 + item bias + sigmoid
// =====================================================================
__global__ void final_k(const float* __restrict__ W3, const float* __restrict__ b3,
                        const float* __restrict__ alpha, const float* __restrict__ beta,
                        float* __restrict__ out, int out_size)
{
    int b = blockIdx.x * blockDim.x + threadIdx.x;
    if (b >= BB) return;
    float acc = b3[0];
#pragma unroll
    for (int k = 0; k < D2; k++) {
        float v  = g_y2[b * D2 + k];
        float xn = (v - g_m4[k]) * g_r4[k];
        float pp = sigf(beta[k] * xn);
        v = v * (pp + alpha[k] * (1.0f - pp));
        acc = fmaf(v, W3[k], acc);
    }
    acc += g_obias[b];
    if (b < out_size) out[b] = acc;
    if (BB + b < out_size) out[BB + b] = sigf_precise(acc);
}

// =====================================================================
// launch
// =====================================================================
extern "C" void kernel_launch(void* const* d_in, const int* in_sizes, int n_in,
                              void* d_out, int out_size)
{
    const int*   user       = (const int*)  d_in[0];
    const int*   item       = (const int*)  d_in[1];
    const int*   history    = (const int*)  d_in[2];
    const int*   length     = (const int*)  d_in[3];
    const int*   cate_list  = (const int*)  d_in[4];
    const float* user_table = (const float*)d_in[5];
    const float* item_table = (const float*)d_in[6];
    const float* cate_table = (const float*)d_in[7];
    const float* item_bias  = (const float*)d_in[8];
    const float* att_W1     = (const float*)d_in[9];
    const float* att_b1     = (const float*)d_in[10];
    const float* att_W2     = (const float*)d_in[11];
    const float* att_b2     = (const float*)d_in[12];
    const float* att_W3     = (const float*)d_in[13];
    const float* att_b3     = (const float*)d_in[14];
    const float* hbn_gamma  = (const float*)d_in[15];
    const float* hbn_beta   = (const float*)d_in[16];
    const float* hist_W     = (const float*)d_in[17];
    const float* hist_b     = (const float*)d_in[18];
    const float* fbn_gamma  = (const float*)d_in[19];
    const float* fbn_beta   = (const float*)d_in[20];
    const float* fc1_W      = (const float*)d_in[21];
    const float* fc1_b      = (const float*)d_in[22];
    const float* d1_alpha   = (const float*)d_in[23];
    const float* d1_beta    = (const float*)d_in[24];
    const float* fc2_W      = (const float*)d_in[25];
    const float* fc2_b      = (const float*)d_in[26];
    const float* d2_alpha   = (const float*)d_in[27];
    const float* d2_beta    = (const float*)d_in[28];
    const float* fc3_W      = (const float*)d_in[29];
    const float* fc3_b      = (const float*)d_in[30];
    float* out = (float*)d_out;

    float *p_q, *p_cq, *p_wac, *p_ha, *p_join, *p_y1, *p_y2;
    float *p_m1, *p_r1, *p_m2, *p_r2, *p_m3, *p_r3, *p_m4, *p_r4;
    cudaGetSymbolAddress((void**)&p_q,    g_q);
    cudaGetSymbolAddress((void**)&p_cq,   g_cq);
    cudaGetSymbolAddress((void**)&p_wac,  g_Wac);
    cudaGetSymbolAddress((void**)&p_ha,   g_hist_attn);
    cudaGetSymbolAddress((void**)&p_join, g_join);
    cudaGetSymbolAddress((void**)&p_y1,   g_y1);
    cudaGetSymbolAddress((void**)&p_y2,   g_y2);
    cudaGetSymbolAddress((void**)&p_m1,   g_m1);
    cudaGetSymbolAddress((void**)&p_r1,   g_r1);
    cudaGetSymbolAddress((void**)&p_m2,   g_m2);
    cudaGetSymbolAddress((void**)&p_r2,   g_r2);
    cudaGetSymbolAddress((void**)&p_m3,   g_m3);
    cudaGetSymbolAddress((void**)&p_r3,   g_r3);
    cudaGetSymbolAddress((void**)&p_m4,   g_m4);
    cudaGetSymbolAddress((void**)&p_r4,   g_r4);

    cudaFuncSetAttribute(att_kernel, cudaFuncAttributeMaxDynamicSharedMemorySize,
                         SMEM_ATT_TOTAL);

    auto smemG = [](int KIN, int JOUT) { return (JOUT + 18) * (KIN + 2) * 4; };
    cudaFuncSetAttribute((const void*)gemm_smemW<128, 80, 0>,
        cudaFuncAttributeMaxDynamicSharedMemorySize, smemG(128, 80));
    cudaFuncSetAttribute((const void*)gemm_smemW<128, 128, 1>,
        cudaFuncAttributeMaxDynamicSharedMemorySize, smemG(128, 128));
    cudaFuncSetAttribute((const void*)gemm_smemW<384, 80, 1>,
        cudaFuncAttributeMaxDynamicSharedMemorySize, smemG(384, 80));
    cudaFuncSetAttribute((const void*)gemm_smemW<80, 40, 2>,
        cudaFuncAttributeMaxDynamicSharedMemorySize, smemG(80, 40));

    // 1-3: prep (att lands in profile slot 4)
    fold_W<<<(KK * D1 + 255) / 256, 256>>>(att_W1, att_W2);
    prep_batch<<<BB, 128>>>(user, item, cate_list, user_table, item_table,
                            cate_table, item_bias);
    gemm_smemW<128, 80, 0><<<BB / 16, 256, smemG(128, 80)>>>(
        p_q, KK, p_wac, att_b1, p_cq, D1, 0, nullptr, nullptr, nullptr, nullptr);

    // 4: ATT-A (balanced half-batch per CTA; 2 CTAs/SM)
    att_kernel<<<2 * BB, 256, SMEM_ATT_TOTAL>>>(history, length, cate_list,
                                                item_table, cate_table,
                                                att_b2, att_W3, att_b3);
    // 5: ATT-B (masked softmax + exact fp32 weighted embedding bag)
    attnbag_kernel<<<BB, 256>>>(history, length, cate_list, item_table, cate_table);

    // tail
    colstats2<<<(KK + 31) / 32, 512>>>(p_ha, BB, KK, p_m1, p_r1);
    gemm_smemW<128, 128, 1><<<BB / 16, 256, smemG(128, 128)>>>(
        p_ha, KK, hist_W, hist_b, p_join, DJ, 256, p_m1, p_r1, hbn_gamma, hbn_beta);
    colstats2<<<(DJ + 31) / 32, 512>>>(p_join, BB, DJ, p_m2, p_r2);
    gemm_smemW<384, 80, 1><<<BB / 16, 256, smemG(384, 80)>>>(
        p_join, DJ, fc1_W, fc1_b, p_y1, D1, 0, p_m2, p_r2, fbn_gamma, fbn_beta);
    colstats2<<<(D1 + 31) / 32, 512>>>(p_y1, BB, D1, p_m3, p_r3);
    gemm_smemW<80, 40, 2><<<BB / 16, 256, smemG(80, 40)>>>(
        p_y1, D1, fc2_W, fc2_b, p_y2, D2, 0, p_m3, p_r3, d1_alpha, d1_beta);
    colstats2<<<(D2 + 31) / 32, 512>>>(p_y2, BB, D2, p_m4, p_r4);
    final_k<<<(BB + 255) / 256, 256>>>(fc3_W, fc3_b, d2_alpha, d2_beta, out, out_size);
}

// round 15
// speedup vs baseline: 1.0856x; 1.0856x over previous
#include <cuda_runtime.h>
#include <cuda_bf16.h>
#include <mma.h>
#include <math.h>
#include <float.h>

using namespace nvcuda;

// ---------------- problem constants ----------------
#define BB 2048
#define TT 200
#define KK 128
#define UD 128
#define D1 80
#define D2 40
#define DJ 384
#define TH 104                   // t per half-CTA (asymmetric split)
#define ALD2 136                 // A/B1 ldm: 272B rows (16 mod 128 -> conflict-free)
#define S1LD 88                  // 176B (48 mod 128)
#define D1LD 88                  // 352B (96 mod 128)
#define D2LD 56                  // 224B (96 mod 128)
#define BN_EPS 1e-3f
#define RSQRT_K 0.08838834764831843f

// ---- ATT-A SMEM layout (bytes) per half-CTA ----
#define A_OFF    0
#define B1S_OFF  30464
#define S1_OFF   52224
#define B2S_OFF  71936
#define MISC_OFF 80384
#define SMEM_ATT_TOTAL 81536

// ---------------- scratch (device globals) ----------
__device__ float g_q[BB * KK];
__device__ float g_cq[BB * D1];
__device__ float g_Wac[KK * D1];
__device__ uint2 g_B1pk[D1 * 64];            // [j][kp]: {bf16x2 Wbc, bf16x2 W1d}
__device__ __nv_bfloat16 g_B2bf[48 * D1];    // [n][k] W2^T padded to 48 n
__device__ float g_attn[BB * 224];           // raw scores (t<len only)
__device__ float g_obias[BB];
__device__ float g_hist_attn[BB * KK];
__device__ float g_join[BB * DJ];
__device__ float g_y1[BB * D1];
__device__ float g_y2[BB * D2];
__device__ float g_m1[KK],  g_r1[KK];
__device__ float g_m2[DJ],  g_r2[DJ];
__device__ float g_m3[D1],  g_r3[D1];
__device__ float g_m4[D2],  g_r4[D2];

// ---------------- helpers ----------------
__device__ __forceinline__ unsigned long long pack2(float x, float y) {
    unsigned long long r;
    asm("mov.b64 %0, {%1, %2};" : "=l"(r) : "f"(x), "f"(y));
    return r;
}
__device__ __forceinline__ float2 unpack2(unsigned long long v) {
    float2 r;
    asm("mov.b64 {%0, %1}, %2;" : "=f"(r.x), "=f"(r.y) : "l"(v));
    return r;
}
__device__ __forceinline__ void fma2(unsigned long long& d, unsigned long long a,
                                     unsigned long long b) {
    asm("fma.rn.f32x2 %0, %1, %2, %0;" : "+l"(d) : "l"(a), "l"(b));
}
__device__ __forceinline__ float sigf(float x) {
    float t;
    asm("tanh.approx.f32 %0, %1;" : "=f"(t) : "f"(x * 0.5f));
    return fmaf(0.5f, t, 0.5f);
}
__device__ __forceinline__ float sigf_precise(float x) {
    return __fdividef(1.0f, 1.0f + __expf(-x));
}
__device__ __forceinline__ unsigned int bf16x2_of(float x, float y) {
    unsigned int r;
    asm("cvt.rn.bf16x2.f32 %0, %2, %1;" : "=r"(r) : "f"(x), "f"(y));
    return r;
}

// =====================================================================
// fold: g_Wac [k][n] + packed bf16 B1 pairs + bf16 B2 [48][80]
// =====================================================================
__global__ void fold_W(const float* __restrict__ W1, const float* __restrict__ W2) {
    int i = blockIdx.x * blockDim.x + threadIdx.x;
    if (i < KK * D1) {
        int k = i / D1, n = i - k * D1;
        g_Wac[i] = W1[(size_t)k * D1 + n] + W1[(size_t)(2 * KK + k) * D1 + n];
    }
    if (i < D1 * 64) {
        int j = i >> 6, k = (i & 63) << 1;
        float wbc0 = W1[(size_t)(KK + k) * D1 + j]     - W1[(size_t)(2 * KK + k) * D1 + j];
        float wbc1 = W1[(size_t)(KK + k + 1) * D1 + j] - W1[(size_t)(2 * KK + k + 1) * D1 + j];
        float w1d0 = W1[(size_t)(3 * KK + k) * D1 + j];
        float w1d1 = W1[(size_t)(3 * KK + k + 1) * D1 + j];
        g_B1pk[i] = make_uint2(bf16x2_of(wbc0, wbc1), bf16x2_of(w1d0, w1d1));
    }
    if (i < 48 * D1) {
        int n = i / D1, k = i - n * D1;
        g_B2bf[i] = (n < D2) ? __float2bfloat16(W2[(size_t)k * D2 + n])
                             : __float2bfloat16(0.0f);
    }
}

__global__ void prep_batch(const int* __restrict__ user, const int* __restrict__ item,
                           const int* __restrict__ cate_list,
                           const float* __restrict__ user_table,
                           const float* __restrict__ item_table,
                           const float* __restrict__ cate_table,
                           const float* __restrict__ item_bias) {
    int b = blockIdx.x, tid = threadIdx.x;
    int it = item[b];
    float qv = (tid < 64) ? item_table[(size_t)it * 64 + tid]
                          : cate_table[(size_t)cate_list[it] * 64 + (tid - 64)];
    g_q[b * KK + tid] = qv;
    g_join[b * DJ + UD + tid] = qv;
    g_join[b * DJ + tid] = user_table[(size_t)user[b] * UD + tid];
    if (tid == 0) g_obias[b] = item_bias[it];
}

// =====================================================================
// SMEM-staged tail GEMM (proven R4)
// =====================================================================
template<int KIN, int JOUT, int MODE>
__global__ __launch_bounds__(256) void gemm_smemW(
    const float* __restrict__ in, int in_stride,
    const float* __restrict__ W, const float* __restrict__ bias,
    float* __restrict__ out, int out_stride, int out_off,
    const float* __restrict__ mean, const float* __restrict__ rstd,
    const float* __restrict__ p1, const float* __restrict__ p2)
{
    constexpr int KP  = KIN + 2;
    constexpr int NR  = 256 / JOUT;
    constexpr int ACT = NR * JOUT;
    constexpr int M   = (16 + NR - 1) / NR;
    extern __shared__ float smg[];
    float* ws = smg;
    float* xs = ws + JOUT * KP;
    const int b0 = blockIdx.x * 16;

    for (int i = threadIdx.x; i < KIN * JOUT; i += 256) {
        int k = i / JOUT, j = i - k * JOUT;
        ws[j * KP + k] = W[i];
    }
    for (int i = threadIdx.x; i < 16 * KIN; i += 256) {
        int r = i / KIN, k = i - r * KIN;
        float v = in[(size_t)(b0 + r) * in_stride + k];
        if constexpr (MODE == 1) {
            v = (v - mean[k]) * rstd[k] * p1[k] + p2[k];
        } else if constexpr (MODE == 2) {
            float xn = (v - mean[k]) * rstd[k];
            float pp = sigf(p2[k] * xn);
            v = v * (pp + p1[k] * (1.0f - pp));
        }
        xs[r * KP + k] = v;
    }
    __syncthreads();

    if (threadIdx.x < ACT) {
        const int j  = threadIdx.x % JOUT;
        const int rg = threadIdx.x / JOUT;
        const float bj = bias[j];
        unsigned long long acc[M];
        const unsigned long long* xpr[M];
#pragma unroll
        for (int m = 0; m < M; m++) {
            acc[m] = 0ULL;
            xpr[m] = (const unsigned long long*)(xs + (rg + NR * m) * KP);
        }
        const unsigned long long* wp = (const unsigned long long*)(ws + j * KP);
#pragma unroll 4
        for (int kp = 0; kp < KIN / 2; kp++) {
            unsigned long long w2 = wp[kp];
#pragma unroll
            for (int m = 0; m < M; m++)
                fma2(acc[m], xpr[m][kp], w2);
        }
#pragma unroll
        for (int m = 0; m < M; m++) {
            int r = rg + NR * m;
            if (r < 16) {
                float2 v = unpack2(acc[m]);
                out[(size_t)(b0 + r) * out_stride + out_off + j] = v.x + v.y + bj;
            }
        }
    }
}

__global__ void colstats2(const float* __restrict__ x, int rows, int cols,
                          float* __restrict__ mean, float* __restrict__ rstd)
{
    __shared__ float ss[16][33], sq[16][33];
    int tx = threadIdx.x & 31, ty = threadIdx.x >> 5;
    int col = blockIdx.x * 32 + tx;
    float s = 0.f, q = 0.f;
    if (col < cols) {
#pragma unroll 8
        for (int r = ty; r < rows; r += 16) {
            float v = x[(size_t)r * cols + col];
            s += v; q = fmaf(v, v, q);
        }
    }
    ss[ty][tx] = s; sq[ty][tx] = q;
    __syncthreads();
    if (ty == 0 && col < cols) {
        float S = 0.f, Q = 0.f;
#pragma unroll
        for (int i = 0; i < 16; i++) { S += ss[i][tx]; Q += sq[i][tx]; }
        float m = S / (float)rows;
        float v = Q / (float)rows - m * m;
        mean[col] = m;
        rstd[col] = rsqrtf(v + BN_EPS);
    }
}

// =====================================================================
// ATT-A: asymmetric half-batch per CTA with early exit. bf16 wmma,
// HFMA2 weff build. grid = 2*BB, 256 threads, 2 CTAs/SM.
// Writes ONLY real scores (t < len); ATT-B applies the mask.
// =====================================================================
__global__ __launch_bounds__(256, 2) void att_kernel(
    const int* __restrict__ history, const int* __restrict__ length,
    const int* __restrict__ cate_list,
    const float* __restrict__ item_table, const float* __restrict__ cate_table,
    const float* __restrict__ b2, const float* __restrict__ W3,
    const float* __restrict__ b3)
{
    extern __shared__ __align__(16) char smc[];
    __nv_bfloat16* a_bf = (__nv_bfloat16*)(smc + A_OFF);    // [112][136]
    float*         d1f  = (float*)(smc + A_OFF);            // overlay [112][88]
    float*         d2f  = (float*)(smc + A_OFF);            // overlay [112][56]
    __nv_bfloat16* b1s  = (__nv_bfloat16*)(smc + B1S_OFF);  // weff [80][136]
    __nv_bfloat16* s1p  = (__nv_bfloat16*)(smc + S1_OFF);   // [112][88]
    __nv_bfloat16* b2s  = (__nv_bfloat16*)(smc + B2S_OFF);  // [48][88]
    unsigned int* qpk = (unsigned int*)(smc + MISC_OFF);    // 64 bf16x2
    float* cqs = (float*)(qpk + 64);                        // 80
    float* w3s = cqs + 80;                                  // 40
    float* b2v = w3s + 40;                                  // 40

    const int bx  = blockIdx.x;
    const int b   = bx >> 1;
    const int h0  = (bx & 1) * TH;                  // asymmetric split
    const int len = length[b];
    const int lenc = min(len - h0, TH);             // rows this CTA computes
    const int tid = threadIdx.x;
    const int wid = tid >> 5;

    if (lenc <= 0) return;                          // fully masked -> free
    const int MT = (lenc + 15) >> 4;                // active m-tiles (1..7)

    // ---- stage small params ----
    if (tid < 64) {
        float2 qv = *(const float2*)(g_q + b * KK + 2 * tid);
        qpk[tid] = bf16x2_of(qv.x, qv.y);
    }
    if (tid < D1) cqs[tid] = g_cq[b * D1 + tid];
    if (tid < D2) { w3s[tid] = W3[tid]; b2v[tid] = b2[tid]; }

    // zero only tail rows [lenc, MT*16), k<128 (16 uint4 per row)
    {
        uint4 z = make_uint4(0, 0, 0, 0);
        int nrows = MT * 16 - lenc;                 // 0..15
        for (int i = tid; i < nrows * 16; i += 256) {
            int r = lenc + i / 16, c = (i & 15) << 3;
            *(uint4*)(a_bf + r * ALD2 + c) = z;
        }
    }
    // stage B2 (80 -> 88 restride)
    for (int i = tid; i < 48 * 10; i += 256) {
        int n = i / 10, c8 = (i % 10) << 3;
        *(uint4*)(b2s + n * S1LD + c8) = *(const uint4*)(g_B2bf + n * D1 + c8);
    }
    __syncthreads();   // qpk ready before weff build

    // ---- weff build: one LDG.64 + HFMA2 + STS.32 per (j, k-pair) ----
    for (int i = tid; i < D1 * 64; i += 256) {      // 20 iterations
        int j = i >> 6, kp2 = i & 63;
        uint2 w = g_B1pk[i];
        __nv_bfloat162 wbc = *reinterpret_cast<__nv_bfloat162*>(&w.x);
        __nv_bfloat162 w1d = *reinterpret_cast<__nv_bfloat162*>(&w.y);
        __nv_bfloat162 qq  = *reinterpret_cast<__nv_bfloat162*>(&qpk[kp2]);
        __nv_bfloat162 r   = __hfma2(qq, w1d, wbc);
        *(__nv_bfloat162*)(b1s + j * ALD2 + 2 * kp2) = r;
    }

    // ---- gather A = hist rows (t local, only t < lenc) ----
    {
        int t = tid >> 1, half = tid & 1;
        if (t < lenc) {
            int hidx = history[b * TT + h0 + t];
            const float4* row = half
                ? (const float4*)(cate_table + (size_t)cate_list[hidx] * 64)
                : (const float4*)(item_table + (size_t)hidx * 64);
            int kb0 = half * 64;
            __nv_bfloat16* arow = a_bf + t * ALD2;
#pragma unroll
            for (int c = 0; c < 16; c++) {
                float4 v = row[c];
                int k = kb0 + 4 * c;
                *(unsigned int*)(arow + k)     = bf16x2_of(v.x, v.y);
                *(unsigned int*)(arow + k + 2) = bf16x2_of(v.z, v.w);
            }
        }
    }
    __syncthreads();

    // ---- layer 1: D1[MT*16 x 80] = A @ weff^T (warp == m-tile) ----
    wmma::fragment<wmma::accumulator, 16, 16, 16, float> acc1[5];
    if (wid < MT) {
#pragma unroll
        for (int nt = 0; nt < 5; nt++) wmma::fill_fragment(acc1[nt], 0.0f);
#pragma unroll
        for (int ks = 0; ks < 8; ks++) {
            wmma::fragment<wmma::matrix_a, 16, 16, 16, __nv_bfloat16, wmma::row_major> af;
            wmma::load_matrix_sync(af, a_bf + wid * 16 * ALD2 + ks * 16, ALD2);
#pragma unroll
            for (int nt = 0; nt < 5; nt++) {
                wmma::fragment<wmma::matrix_b, 16, 16, 16, __nv_bfloat16, wmma::col_major> bf;
                wmma::load_matrix_sync(bf, b1s + nt * 16 * ALD2 + ks * 16, ALD2);
                wmma::mma_sync(acc1[nt], af, bf, acc1[nt]);
            }
        }
    }
    __syncthreads();   // A + B1 dead; accumulators in regs
    if (wid < MT) {
#pragma unroll
        for (int nt = 0; nt < 5; nt++)
            wmma::store_matrix_sync(d1f + wid * 16 * D1LD + nt * 16, acc1[nt], D1LD,
                                    wmma::mem_row_major);
    }
    __syncthreads();

    // ---- epilogue 1: S1 = sigf(D1 + cq) bf16 ----
    {
        int t = tid >> 1, half = tid & 1;
        if (t < MT * 16) {
            const float* dr = d1f + t * D1LD + half * 40;
            __nv_bfloat16* sr = s1p + t * S1LD + half * 40;
            const float* cq = cqs + half * 40;
#pragma unroll
            for (int jp = 0; jp < 20; jp++) {
                float v0 = sigf(dr[2 * jp]     + cq[2 * jp]);
                float v1 = sigf(dr[2 * jp + 1] + cq[2 * jp + 1]);
                *(unsigned int*)(sr + 2 * jp) = bf16x2_of(v0, v1);
            }
        }
    }
    __syncthreads();

    // ---- layer 2: D2[MT*16 x 48] = S1 @ B2^T ----
    for (int idx = wid; idx < MT * 3; idx += 8) {
        int mt = idx / 3, nt = idx - 3 * mt;
        wmma::fragment<wmma::accumulator, 16, 16, 16, float> acc2;
        wmma::fill_fragment(acc2, 0.0f);
#pragma unroll
        for (int ks = 0; ks < 5; ks++) {
            wmma::fragment<wmma::matrix_a, 16, 16, 16, __nv_bfloat16, wmma::row_major> af;
            wmma::fragment<wmma::matrix_b, 16, 16, 16, __nv_bfloat16, wmma::col_major> bf;
            wmma::load_matrix_sync(af, s1p + mt * 16 * S1LD + ks * 16, S1LD);
            wmma::load_matrix_sync(bf, b2s + nt * 16 * S1LD + ks * 16, S1LD);
            wmma::mma_sync(acc2, af, bf, acc2);
        }
        wmma::store_matrix_sync(d2f + mt * 16 * D2LD + nt * 16, acc2, D2LD,
                                wmma::mem_row_major);
    }
    __syncthreads();

    // ---- layer 3: real scores only ----
    if (tid < lenc) {
        float score = b3[0];
        const float* dr = d2f + tid * D2LD;
#pragma unroll
        for (int n = 0; n < D2; n++)
            score = fmaf(sigf(dr[n] + b2v[n]), w3s[n], score);
        g_attn[b * 224 + h0 + tid] = score * RSQRT_K;
    }
}

// =====================================================================
// ATT-B: masked softmax + exact fp32 weighted embedding bag
// =====================================================================
__global__ __launch_bounds__(256) void attnbag_kernel(
    const int* __restrict__ history, const int* __restrict__ length,
    const int* __restrict__ cate_list,
    const float* __restrict__ item_table, const float* __restrict__ cate_table)
{
    __shared__ float part[8][128];
    __shared__ float red[256];
    __shared__ float attn_s[224];
    const int b = blockIdx.x;
    const int tid = threadIdx.x;
    const int lane = tid & 31, w = tid >> 5;
    const int len = length[b];

    float sc = (tid < len) ? g_attn[b * 224 + tid] : -FLT_MAX;
    red[tid] = sc;
    __syncthreads();
#pragma unroll
    for (int s = 128; s > 0; s >>= 1) {
        if (tid < s) red[tid] = fmaxf(red[tid], red[tid + s]);
        __syncthreads();
    }
    const float mx = red[0];
    __syncthreads();
    float p = (tid < len) ? __expf(sc - mx) : 0.0f;
    red[tid] = p;
    __syncthreads();
#pragma unroll
    for (int s = 128; s > 0; s >>= 1) {
        if (tid < s) red[tid] += red[tid + s];
        __syncthreads();
    }
    const float inv = 1.0f / red[0];
    if (tid < 224) attn_s[tid] = (tid < len) ? p * inv : 0.0f;
    __syncthreads();

    float4 acc = make_float4(0.f, 0.f, 0.f, 0.f);
    for (int t = w; t < len; t += 8) {
        float a = attn_s[t];
        int hidx = history[b * TT + t];
        const float4* row = (lane < 16)
            ? (const float4*)(item_table + (size_t)hidx * 64) + lane
            : (const float4*)(cate_table + (size_t)cate_list[hidx] * 64) + (lane - 16);
        float4 v = *row;
        acc.x = fmaf(a, v.x, acc.x);
        acc.y = fmaf(a, v.y, acc.y);
        acc.z = fmaf(a, v.z, acc.z);
        acc.w = fmaf(a, v.w, acc.w);
    }
    ((float4*)part[w])[lane] = acc;
    __syncthreads();
    if (tid < 128) {
        float s = 0.f;
#pragma unroll
        for (int i = 0; i < 8; i++) s += part[i][tid];
        g_hist_attn[b * KK + tid] = s;
    }
}

// =====================================================================
// final: dice + fc3 + item bias + sigmoid
// =====================================================================
__global__ void final_k(const float* __restrict__ W3, const float* __restrict__ b3,
                        const float* __restrict__ alpha, const float* __restrict__ beta,
                        float* __restrict__ out, int out_size)
{
    int b = blockIdx.x * blockDim.x + threadIdx.x;
    if (b >= BB) return;
    float acc = b3[0];
#pragma unroll
    for (int k = 0; k < D2; k++) {
        float v  = g_y2[b * D2 + k];
        float xn = (v - g_m4[k]) * g_r4[k];
        float pp = sigf(beta[k] * xn);
        v = v * (pp + alpha[k] * (1.0f - pp));
        acc = fmaf(v, W3[k], acc);
    }
    acc += g_obias[b];
    if (b < out_size) out[b] = acc;
    if (BB + b < out_size) out[BB + b] = sigf_precise(acc);
}

// =====================================================================
// launch
// =====================================================================
extern "C" void kernel_launch(void* const* d_in, const int* in_sizes, int n_in,
                              void* d_out, int out_size)
{
    const int*   user       = (const int*)  d_in[0];
    const int*   item       = (const int*)  d_in[1];
    const int*   history    = (const int*)  d_in[2];
    const int*   length     = (const int*)  d_in[3];
    const int*   cate_list  = (const int*)  d_in[4];
    const float* user_table = (const float*)d_in[5];
    const float* item_table = (const float*)d_in[6];
    const float* cate_table = (const float*)d_in[7];
    const float* item_bias  = (const float*)d_in[8];
    const float* att_W1     = (const float*)d_in[9];
    const float* att_b1     = (const float*)d_in[10];
    const float* att_W2     = (const float*)d_in[11];
    const float* att_b2     = (const float*)d_in[12];
    const float* att_W3     = (const float*)d_in[13];
    const float* att_b3     = (const float*)d_in[14];
    const float* hbn_gamma  = (const float*)d_in[15];
    const float* hbn_beta   = (const float*)d_in[16];
    const float* hist_W     = (const float*)d_in[17];
    const float* hist_b     = (const float*)d_in[18];
    const float* fbn_gamma  = (const float*)d_in[19];
    const float* fbn_beta   = (const float*)d_in[20];
    const float* fc1_W      = (const float*)d_in[21];
    const float* fc1_b      = (const float*)d_in[22];
    const float* d1_alpha   = (const float*)d_in[23];
    const float* d1_beta    = (const float*)d_in[24];
    const float* fc2_W      = (const float*)d_in[25];
    const float* fc2_b      = (const float*)d_in[26];
    const float* d2_alpha   = (const float*)d_in[27];
    const float* d2_beta    = (const float*)d_in[28];
    const float* fc3_W      = (const float*)d_in[29];
    const float* fc3_b      = (const float*)d_in[30];
    float* out = (float*)d_out;

    float *p_q, *p_cq, *p_wac, *p_ha, *p_join, *p_y1, *p_y2;
    float *p_m1, *p_r1, *p_m2, *p_r2, *p_m3, *p_r3, *p_m4, *p_r4;
    cudaGetSymbolAddress((void**)&p_q,    g_q);
    cudaGetSymbolAddress((void**)&p_cq,   g_cq);
    cudaGetSymbolAddress((void**)&p_wac,  g_Wac);
    cudaGetSymbolAddress((void**)&p_ha,   g_hist_attn);
    cudaGetSymbolAddress((void**)&p_join, g_join);
    cudaGetSymbolAddress((void**)&p_y1,   g_y1);
    cudaGetSymbolAddress((void**)&p_y2,   g_y2);
    cudaGetSymbolAddress((void**)&p_m1,   g_m1);
    cudaGetSymbolAddress((void**)&p_r1,   g_r1);
    cudaGetSymbolAddress((void**)&p_m2,   g_m2);
    cudaGetSymbolAddress((void**)&p_r2,   g_r2);
    cudaGetSymbolAddress((void**)&p_m3,   g_m3);
    cudaGetSymbolAddress((void**)&p_r3,   g_r3);
    cudaGetSymbolAddress((void**)&p_m4,   g_m4);
    cudaGetSymbolAddress((void**)&p_r4,   g_r4);

    cudaFuncSetAttribute(att_kernel, cudaFuncAttributeMaxDynamicSharedMemorySize,
                         SMEM_ATT_TOTAL);

    auto smemG = [](int KIN, int JOUT) { return (JOUT + 18) * (KIN + 2) * 4; };
    cudaFuncSetAttribute((const void*)gemm_smemW<128, 80, 0>,
        cudaFuncAttributeMaxDynamicSharedMemorySize, smemG(128, 80));
    cudaFuncSetAttribute((const void*)gemm_smemW<128, 128, 1>,
        cudaFuncAttributeMaxDynamicSharedMemorySize, smemG(128, 128));
    cudaFuncSetAttribute((const void*)gemm_smemW<384, 80, 1>,
        cudaFuncAttributeMaxDynamicSharedMemorySize, smemG(384, 80));
    cudaFuncSetAttribute((const void*)gemm_smemW<80, 40, 2>,
        cudaFuncAttributeMaxDynamicSharedMemorySize, smemG(80, 40));

    // 1-3: prep (att lands in profile slot 4)
    fold_W<<<(KK * D1 + 255) / 256, 256>>>(att_W1, att_W2);
    prep_batch<<<BB, 128>>>(user, item, cate_list, user_table, item_table,
                            cate_table, item_bias);
    gemm_smemW<128, 80, 0><<<BB / 16, 256, smemG(128, 80)>>>(
        p_q, KK, p_wac, att_b1, p_cq, D1, 0, nullptr, nullptr, nullptr, nullptr);

    // 4: ATT-A (asymmetric half-batch per CTA w/ early exit; 2 CTAs/SM)
    att_kernel<<<2 * BB, 256, SMEM_ATT_TOTAL>>>(history, length, cate_list,
                                                item_table, cate_table,
                                                att_b2, att_W3, att_b3);
    // 5: ATT-B (masked softmax + exact fp32 weighted embedding bag)
    attnbag_kernel<<<BB, 256>>>(history, length, cate_list, item_table, cate_table);

    // tail
    colstats2<<<(KK + 31) / 32, 512>>>(p_ha, BB, KK, p_m1, p_r1);
    gemm_smemW<128, 128, 1><<<BB / 16, 256, smemG(128, 128)>>>(
        p_ha, KK, hist_W, hist_b, p_join, DJ, 256, p_m1, p_r1, hbn_gamma, hbn_beta);
    colstats2<<<(DJ + 31) / 32, 512>>>(p_join, BB, DJ, p_m2, p_r2);
    gemm_smemW<384, 80, 1><<<BB / 16, 256, smemG(384, 80)>>>(
        p_join, DJ, fc1_W, fc1_b, p_y1, D1, 0, p_m2, p_r2, fbn_gamma, fbn_beta);
    colstats2<<<(D1 + 31) / 32, 512>>>(p_y1, BB, D1, p_m3, p_r3);
    gemm_smemW<80, 40, 2><<<BB / 16, 256, smemG(80, 40)>>>(
        p_y1, D1, fc2_W, fc2_b, p_y2, D2, 0, p_m3, p_r3, d1_alpha, d1_beta);
    colstats2<<<(D2 + 31) / 32, 512>>>(p_y2, BB, D2, p_m4, p_r4);
    final_k<<<(BB + 255) / 256, 256>>>(fc3_W, fc3_b, d2_alpha, d2_beta, out, out_size);
}

// round 16
// speedup vs baseline: 1.1045x; 1.0175x over previous
#include <cuda_runtime.h>
#include <cuda_bf16.h>
#include <mma.h>
#include <math.h>
#include <float.h>

using namespace nvcuda;

// ---------------- problem constants ----------------
#define BB 2048
#define TT 200
#define KK 128
#define UD 128
#define D1 80
#define D2 40
#define DJ 384
#define TH 104                   // t per half-CTA (asymmetric split)
#define ALD2 136                 // A/B1 ldm: 272B rows (16 mod 128 -> conflict-free)
#define S1LD 88                  // 176B (48 mod 128)
#define D1LD 88                  // 352B (96 mod 128)
#define D2LD 56                  // 224B (96 mod 128)
#define BN_EPS 1e-3f
#define RSQRT_K 0.08838834764831843f

// ---- ATT-A SMEM layout (bytes), compacted for 3 CTAs/SM ----
// timeline: [A|B1] -> MMA1 -> D1 overlays [0,39424) -> epi writes S1 ->
//           MMA2 reads S1,B2, writes D2 [0,25088) -> layer3 -> bag scratch [0,...)
#define A_OFF    0               // A bf16 [112][136] = 30464
#define B1S_OFF  30464           // weff bf16 [80][136] = 21760 (ends 52224)
#define S1_OFF   39424           // S1 bf16 [112][88] = 19712 (after D1 region)
#define B2S_OFF  59136           // B2 bf16 [48][88] = 8448
#define MISC_OFF 67584           // qpk 256B + cqs 320 + w3s 160 + b2v 160 + flag 4
#define SMEM_ATT_TOTAL 68736

// ---------------- scratch (device globals) ----------
__device__ float g_q[BB * KK];
__device__ float g_cq[BB * D1];
__device__ float g_Wac[KK * D1];
__device__ uint2 g_B1pk[D1 * 64];            // [j][kp]: {bf16x2 Wbc, bf16x2 W1d}
__device__ __nv_bfloat16 g_B2bf[48 * D1];    // [n][k] W2^T padded to 48 n
__device__ float g_attn[BB * 224];           // raw scores (t<len only)
__device__ int   g_ctr[BB];                  // per-batch arrival counter
__device__ float g_obias[BB];
__device__ float g_hist_attn[BB * KK];
__device__ float g_join[BB * DJ];
__device__ float g_y1[BB * D1];
__device__ float g_y2[BB * D2];
__device__ float g_m1[KK],  g_r1[KK];
__device__ float g_m2[DJ],  g_r2[DJ];
__device__ float g_m3[D1],  g_r3[D1];
__device__ float g_m4[D2],  g_r4[D2];

// ---------------- helpers ----------------
__device__ __forceinline__ unsigned long long pack2(float x, float y) {
    unsigned long long r;
    asm("mov.b64 %0, {%1, %2};" : "=l"(r) : "f"(x), "f"(y));
    return r;
}
__device__ __forceinline__ float2 unpack2(unsigned long long v) {
    float2 r;
    asm("mov.b64 {%0, %1}, %2;" : "=f"(r.x), "=f"(r.y) : "l"(v));
    return r;
}
__device__ __forceinline__ void fma2(unsigned long long& d, unsigned long long a,
                                     unsigned long long b) {
    asm("fma.rn.f32x2 %0, %1, %2, %0;" : "+l"(d) : "l"(a), "l"(b));
}
__device__ __forceinline__ float sigf(float x) {
    float t;
    asm("tanh.approx.f32 %0, %1;" : "=f"(t) : "f"(x * 0.5f));
    return fmaf(0.5f, t, 0.5f);
}
__device__ __forceinline__ float sigf_precise(float x) {
    return __fdividef(1.0f, 1.0f + __expf(-x));
}
__device__ __forceinline__ unsigned int bf16x2_of(float x, float y) {
    unsigned int r;
    asm("cvt.rn.bf16x2.f32 %0, %2, %1;" : "=r"(r) : "f"(x), "f"(y));
    return r;
}

// =====================================================================
// fold: g_Wac [k][n] + packed bf16 B1 pairs + bf16 B2 [48][80]
// =====================================================================
__global__ void fold_W(const float* __restrict__ W1, const float* __restrict__ W2) {
    int i = blockIdx.x * blockDim.x + threadIdx.x;
    if (i < KK * D1) {
        int k = i / D1, n = i - k * D1;
        g_Wac[i] = W1[(size_t)k * D1 + n] + W1[(size_t)(2 * KK + k) * D1 + n];
    }
    if (i < D1 * 64) {
        int j = i >> 6, k = (i & 63) << 1;
        float wbc0 = W1[(size_t)(KK + k) * D1 + j]     - W1[(size_t)(2 * KK + k) * D1 + j];
        float wbc1 = W1[(size_t)(KK + k + 1) * D1 + j] - W1[(size_t)(2 * KK + k + 1) * D1 + j];
        float w1d0 = W1[(size_t)(3 * KK + k) * D1 + j];
        float w1d1 = W1[(size_t)(3 * KK + k + 1) * D1 + j];
        g_B1pk[i] = make_uint2(bf16x2_of(wbc0, wbc1), bf16x2_of(w1d0, w1d1));
    }
    if (i < 48 * D1) {
        int n = i / D1, k = i - n * D1;
        g_B2bf[i] = (n < D2) ? __float2bfloat16(W2[(size_t)k * D2 + n])
                             : __float2bfloat16(0.0f);
    }
}

__global__ void prep_batch(const int* __restrict__ user, const int* __restrict__ item,
                           const int* __restrict__ cate_list,
                           const float* __restrict__ user_table,
                           const float* __restrict__ item_table,
                           const float* __restrict__ cate_table,
                           const float* __restrict__ item_bias) {
    int b = blockIdx.x, tid = threadIdx.x;
    int it = item[b];
    float qv = (tid < 64) ? item_table[(size_t)it * 64 + tid]
                          : cate_table[(size_t)cate_list[it] * 64 + (tid - 64)];
    g_q[b * KK + tid] = qv;
    g_join[b * DJ + UD + tid] = qv;
    g_join[b * DJ + tid] = user_table[(size_t)user[b] * UD + tid];
    if (tid == 0) { g_obias[b] = item_bias[it]; g_ctr[b] = 0; }
}

// =====================================================================
// SMEM-staged tail GEMM (proven R4)
// =====================================================================
template<int KIN, int JOUT, int MODE>
__global__ __launch_bounds__(256) void gemm_smemW(
    const float* __restrict__ in, int in_stride,
    const float* __restrict__ W, const float* __restrict__ bias,
    float* __restrict__ out, int out_stride, int out_off,
    const float* __restrict__ mean, const float* __restrict__ rstd,
    const float* __restrict__ p1, const float* __restrict__ p2)
{
    constexpr int KP  = KIN + 2;
    constexpr int NR  = 256 / JOUT;
    constexpr int ACT = NR * JOUT;
    constexpr int M   = (16 + NR - 1) / NR;
    extern __shared__ float smg[];
    float* ws = smg;
    float* xs = ws + JOUT * KP;
    const int b0 = blockIdx.x * 16;

    for (int i = threadIdx.x; i < KIN * JOUT; i += 256) {
        int k = i / JOUT, j = i - k * JOUT;
        ws[j * KP + k] = W[i];
    }
    for (int i = threadIdx.x; i < 16 * KIN; i += 256) {
        int r = i / KIN, k = i - r * KIN;
        float v = in[(size_t)(b0 + r) * in_stride + k];
        if constexpr (MODE == 1) {
            v = (v - mean[k]) * rstd[k] * p1[k] + p2[k];
        } else if constexpr (MODE == 2) {
            float xn = (v - mean[k]) * rstd[k];
            float pp = sigf(p2[k] * xn);
            v = v * (pp + p1[k] * (1.0f - pp));
        }
        xs[r * KP + k] = v;
    }
    __syncthreads();

    if (threadIdx.x < ACT) {
        const int j  = threadIdx.x % JOUT;
        const int rg = threadIdx.x / JOUT;
        const float bj = bias[j];
        unsigned long long acc[M];
        const unsigned long long* xpr[M];
#pragma unroll
        for (int m = 0; m < M; m++) {
            acc[m] = 0ULL;
            xpr[m] = (const unsigned long long*)(xs + (rg + NR * m) * KP);
        }
        const unsigned long long* wp = (const unsigned long long*)(ws + j * KP);
#pragma unroll 4
        for (int kp = 0; kp < KIN / 2; kp++) {
            unsigned long long w2 = wp[kp];
#pragma unroll
            for (int m = 0; m < M; m++)
                fma2(acc[m], xpr[m][kp], w2);
        }
#pragma unroll
        for (int m = 0; m < M; m++) {
            int r = rg + NR * m;
            if (r < 16) {
                float2 v = unpack2(acc[m]);
                out[(size_t)(b0 + r) * out_stride + out_off + j] = v.x + v.y + bj;
            }
        }
    }
}

__global__ void colstats2(const float* __restrict__ x, int rows, int cols,
                          float* __restrict__ mean, float* __restrict__ rstd)
{
    __shared__ float ss[16][33], sq[16][33];
    int tx = threadIdx.x & 31, ty = threadIdx.x >> 5;
    int col = blockIdx.x * 32 + tx;
    float s = 0.f, q = 0.f;
    if (col < cols) {
#pragma unroll 8
        for (int r = ty; r < rows; r += 16) {
            float v = x[(size_t)r * cols + col];
            s += v; q = fmaf(v, v, q);
        }
    }
    ss[ty][tx] = s; sq[ty][tx] = q;
    __syncthreads();
    if (ty == 0 && col < cols) {
        float S = 0.f, Q = 0.f;
#pragma unroll
        for (int i = 0; i < 16; i++) { S += ss[i][tx]; Q += sq[i][tx]; }
        float m = S / (float)rows;
        float v = Q / (float)rows - m * m;
        mean[col] = m;
        rstd[col] = rsqrtf(v + BN_EPS);
    }
}

// =====================================================================
// ATT: asymmetric half-batch per CTA w/ early exit; last-arriving CTA
// of each batch also does masked softmax + exact fp32 bag (fused ATT-B).
// grid = 2*BB, 256 threads, 68.7KB smem -> 3 CTAs/SM.
// =====================================================================
__global__ __launch_bounds__(256, 3) void att_kernel(
    const int* __restrict__ history, const int* __restrict__ length,
    const int* __restrict__ cate_list,
    const float* __restrict__ item_table, const float* __restrict__ cate_table,
    const float* __restrict__ b2, const float* __restrict__ W3,
    const float* __restrict__ b3)
{
    extern __shared__ __align__(16) char smc[];
    __nv_bfloat16* a_bf = (__nv_bfloat16*)(smc + A_OFF);    // [112][136]
    float*         d1f  = (float*)(smc + A_OFF);            // overlay [112][88]
    float*         d2f  = (float*)(smc + A_OFF);            // overlay [112][56]
    __nv_bfloat16* b1s  = (__nv_bfloat16*)(smc + B1S_OFF);  // weff [80][136]
    __nv_bfloat16* s1p  = (__nv_bfloat16*)(smc + S1_OFF);   // [112][88]
    __nv_bfloat16* b2s  = (__nv_bfloat16*)(smc + B2S_OFF);  // [48][88]
    unsigned int* qpk = (unsigned int*)(smc + MISC_OFF);    // 64 bf16x2
    float* cqs = (float*)(qpk + 64);                        // 80
    float* w3s = cqs + 80;                                  // 40
    float* b2v = w3s + 40;                                  // 40
    int*   s_flag = (int*)(b2v + 40);

    const int bx  = blockIdx.x;
    const int b   = bx >> 1;
    const int h0  = (bx & 1) * TH;                  // asymmetric split
    const int len = length[b];
    const int lenc = min(len - h0, TH);             // rows this CTA computes
    const int tid = threadIdx.x;
    const int wid = tid >> 5;

    if (lenc <= 0) return;                          // fully masked -> free
    const int MT = (lenc + 15) >> 4;                // active m-tiles (1..7)

    // ---- stage small params ----
    if (tid < 64) {
        float2 qv = *(const float2*)(g_q + b * KK + 2 * tid);
        qpk[tid] = bf16x2_of(qv.x, qv.y);
    }
    if (tid < D1) cqs[tid] = g_cq[b * D1 + tid];
    if (tid < D2) { w3s[tid] = W3[tid]; b2v[tid] = b2[tid]; }

    // zero only tail rows [lenc, MT*16), k<128
    {
        uint4 z = make_uint4(0, 0, 0, 0);
        int nrows = MT * 16 - lenc;                 // 0..15
        for (int i = tid; i < nrows * 16; i += 256) {
            int r = lenc + i / 16, c = (i & 15) << 3;
            *(uint4*)(a_bf + r * ALD2 + c) = z;
        }
    }
    // stage B2 (80 -> 88 restride)
    for (int i = tid; i < 48 * 10; i += 256) {
        int n = i / 10, c8 = (i % 10) << 3;
        *(uint4*)(b2s + n * S1LD + c8) = *(const uint4*)(g_B2bf + n * D1 + c8);
    }
    __syncthreads();   // qpk ready before weff build

    // ---- weff build: one LDG.64 + HFMA2 + STS.32 per (j, k-pair) ----
    for (int i = tid; i < D1 * 64; i += 256) {
        int j = i >> 6, kp2 = i & 63;
        uint2 w = g_B1pk[i];
        __nv_bfloat162 wbc = *reinterpret_cast<__nv_bfloat162*>(&w.x);
        __nv_bfloat162 w1d = *reinterpret_cast<__nv_bfloat162*>(&w.y);
        __nv_bfloat162 qq  = *reinterpret_cast<__nv_bfloat162*>(&qpk[kp2]);
        __nv_bfloat162 r   = __hfma2(qq, w1d, wbc);
        *(__nv_bfloat162*)(b1s + j * ALD2 + 2 * kp2) = r;
    }

    // ---- gather A = hist rows ----
    {
        int t = tid >> 1, half = tid & 1;
        if (t < lenc) {
            int hidx = history[b * TT + h0 + t];
            const float4* row = half
                ? (const float4*)(cate_table + (size_t)cate_list[hidx] * 64)
                : (const float4*)(item_table + (size_t)hidx * 64);
            int kb0 = half * 64;
            __nv_bfloat16* arow = a_bf + t * ALD2;
#pragma unroll
            for (int c = 0; c < 16; c++) {
                float4 v = row[c];
                int k = kb0 + 4 * c;
                *(unsigned int*)(arow + k)     = bf16x2_of(v.x, v.y);
                *(unsigned int*)(arow + k + 2) = bf16x2_of(v.z, v.w);
            }
        }
    }
    __syncthreads();

    // ---- layer 1: D1[MT*16 x 80] = A @ weff^T (warp == m-tile) ----
    wmma::fragment<wmma::accumulator, 16, 16, 16, float> acc1[5];
    if (wid < MT) {
#pragma unroll
        for (int nt = 0; nt < 5; nt++) wmma::fill_fragment(acc1[nt], 0.0f);
#pragma unroll
        for (int ks = 0; ks < 8; ks++) {
            wmma::fragment<wmma::matrix_a, 16, 16, 16, __nv_bfloat16, wmma::row_major> af;
            wmma::load_matrix_sync(af, a_bf + wid * 16 * ALD2 + ks * 16, ALD2);
#pragma unroll
            for (int nt = 0; nt < 5; nt++) {
                wmma::fragment<wmma::matrix_b, 16, 16, 16, __nv_bfloat16, wmma::col_major> bf;
                wmma::load_matrix_sync(bf, b1s + nt * 16 * ALD2 + ks * 16, ALD2);
                wmma::mma_sync(acc1[nt], af, bf, acc1[nt]);
            }
        }
    }
    __syncthreads();   // A + B1 dead; accumulators in regs
    if (wid < MT) {
#pragma unroll
        for (int nt = 0; nt < 5; nt++)
            wmma::store_matrix_sync(d1f + wid * 16 * D1LD + nt * 16, acc1[nt], D1LD,
                                    wmma::mem_row_major);
    }
    __syncthreads();

    // ---- epilogue 1: S1 = sigf(D1 + cq) bf16 ----
    {
        int t = tid >> 1, half = tid & 1;
        if (t < MT * 16) {
            const float* dr = d1f + t * D1LD + half * 40;
            __nv_bfloat16* sr = s1p + t * S1LD + half * 40;
            const float* cq = cqs + half * 40;
#pragma unroll
            for (int jp = 0; jp < 20; jp++) {
                float v0 = sigf(dr[2 * jp]     + cq[2 * jp]);
                float v1 = sigf(dr[2 * jp + 1] + cq[2 * jp + 1]);
                *(unsigned int*)(sr + 2 * jp) = bf16x2_of(v0, v1);
            }
        }
    }
    __syncthreads();

    // ---- layer 2: D2[MT*16 x 48] = S1 @ B2^T ----
    for (int idx = wid; idx < MT * 3; idx += 8) {
        int mt = idx / 3, nt = idx - 3 * mt;
        wmma::fragment<wmma::accumulator, 16, 16, 16, float> acc2;
        wmma::fill_fragment(acc2, 0.0f);
#pragma unroll
        for (int ks = 0; ks < 5; ks++) {
            wmma::fragment<wmma::matrix_a, 16, 16, 16, __nv_bfloat16, wmma::row_major> af;
            wmma::fragment<wmma::matrix_b, 16, 16, 16, __nv_bfloat16, wmma::col_major> bf;
            wmma::load_matrix_sync(af, s1p + mt * 16 * S1LD + ks * 16, S1LD);
            wmma::load_matrix_sync(bf, b2s + nt * 16 * S1LD + ks * 16, S1LD);
            wmma::mma_sync(acc2, af, bf, acc2);
        }
        wmma::store_matrix_sync(d2f + mt * 16 * D2LD + nt * 16, acc2, D2LD,
                                wmma::mem_row_major);
    }
    __syncthreads();

    // ---- layer 3: real scores ----
    if (tid < lenc) {
        float score = b3[0];
        const float* dr = d2f + tid * D2LD;
#pragma unroll
        for (int n = 0; n < D2; n++)
            score = fmaf(sigf(dr[n] + b2v[n]), w3s[n], score);
        g_attn[b * 224 + h0 + tid] = score * RSQRT_K;
    }

    // ---- arrival protocol: last CTA of batch does softmax + bag ----
    __threadfence();
    __syncthreads();                 // D2 dead after this; region0 reusable
    if (tid == 0) {
        int need = (len > TH) ? 2 : 1;
        int old = atomicAdd(&g_ctr[b], 1);
        *s_flag = (old == need - 1) ? 1 : 0;
    }
    __syncthreads();
    if (*s_flag == 0) return;

    // ---- fused ATT-B: masked softmax + exact fp32 bag (scratch = region0) ----
    float* part  = (float*)smc;          // [8][128]
    float* red   = part + 1024;          // 256
    float* attps = red + 256;            // 224

    float sc = (tid < len) ? __ldcg(g_attn + b * 224 + tid) : -FLT_MAX;
    red[tid] = sc;
    __syncthreads();
#pragma unroll
    for (int s = 128; s > 0; s >>= 1) {
        if (tid < s) red[tid] = fmaxf(red[tid], red[tid + s]);
        __syncthreads();
    }
    const float mx = red[0];
    __syncthreads();
    float p = (tid < len) ? __expf(sc - mx) : 0.0f;
    red[tid] = p;
    __syncthreads();
#pragma unroll
    for (int s = 128; s > 0; s >>= 1) {
        if (tid < s) red[tid] += red[tid + s];
        __syncthreads();
    }
    const float inv = 1.0f / red[0];
    if (tid < 224) attps[tid] = (tid < len) ? p * inv : 0.0f;
    __syncthreads();

    {
        const int lane = tid & 31, w = tid >> 5;
        float4 acc = make_float4(0.f, 0.f, 0.f, 0.f);
        for (int t = w; t < len; t += 8) {
            float a = attps[t];
            int hidx = history[b * TT + t];
            const float4* row = (lane < 16)
                ? (const float4*)(item_table + (size_t)hidx * 64) + lane
                : (const float4*)(cate_table + (size_t)cate_list[hidx] * 64) + (lane - 16);
            float4 v = *row;
            acc.x = fmaf(a, v.x, acc.x);
            acc.y = fmaf(a, v.y, acc.y);
            acc.z = fmaf(a, v.z, acc.z);
            acc.w = fmaf(a, v.w, acc.w);
        }
        ((float4*)(part + w * 128))[lane] = acc;
        __syncthreads();
        if (tid < 128) {
            float s = 0.f;
#pragma unroll
            for (int i = 0; i < 8; i++) s += part[i * 128 + tid];
            g_hist_attn[b * KK + tid] = s;
        }
    }
}

// =====================================================================
// final: dice + fc3 + item bias + sigmoid
// =====================================================================
__global__ void final_k(const float* __restrict__ W3, const float* __restrict__ b3,
                        const float* __restrict__ alpha, const float* __restrict__ beta,
                        float* __restrict__ out, int out_size)
{
    int b = blockIdx.x * blockDim.x + threadIdx.x;
    if (b >= BB) return;
    float acc = b3[0];
#pragma unroll
    for (int k = 0; k < D2; k++) {
        float v  = g_y2[b * D2 + k];
        float xn = (v - g_m4[k]) * g_r4[k];
        float pp = sigf(beta[k] * xn);
        v = v * (pp + alpha[k] * (1.0f - pp));
        acc = fmaf(v, W3[k], acc);
    }
    acc += g_obias[b];
    if (b < out_size) out[b] = acc;
    if (BB + b < out_size) out[BB + b] = sigf_precise(acc);
}

// =====================================================================
// launch
// =====================================================================
extern "C" void kernel_launch(void* const* d_in, const int* in_sizes, int n_in,
                              void* d_out, int out_size)
{
    const int*   user       = (const int*)  d_in[0];
    const int*   item       = (const int*)  d_in[1];
    const int*   history    = (const int*)  d_in[2];
    const int*   length     = (const int*)  d_in[3];
    const int*   cate_list  = (const int*)  d_in[4];
    const float* user_table = (const float*)d_in[5];
    const float* item_table = (const float*)d_in[6];
    const float* cate_table = (const float*)d_in[7];
    const float* item_bias  = (const float*)d_in[8];
    const float* att_W1     = (const float*)d_in[9];
    const float* att_b1     = (const float*)d_in[10];
    const float* att_W2     = (const float*)d_in[11];
    const float* att_b2     = (const float*)d_in[12];
    const float* att_W3     = (const float*)d_in[13];
    const float* att_b3     = (const float*)d_in[14];
    const float* hbn_gamma  = (const float*)d_in[15];
    const float* hbn_beta   = (const float*)d_in[16];
    const float* hist_W     = (const float*)d_in[17];
    const float* hist_b     = (const float*)d_in[18];
    const float* fbn_gamma  = (const float*)d_in[19];
    const float* fbn_beta   = (const float*)d_in[20];
    const float* fc1_W      = (const float*)d_in[21];
    const float* fc1_b      = (const float*)d_in[22];
    const float* d1_alpha   = (const float*)d_in[23];
    const float* d1_beta    = (const float*)d_in[24];
    const float* fc2_W      = (const float*)d_in[25];
    const float* fc2_b      = (const float*)d_in[26];
    const float* d2_alpha   = (const float*)d_in[27];
    const float* d2_beta    = (const float*)d_in[28];
    const float* fc3_W      = (const float*)d_in[29];
    const float* fc3_b      = (const float*)d_in[30];
    float* out = (float*)d_out;

    float *p_q, *p_cq, *p_wac, *p_ha, *p_join, *p_y1, *p_y2;
    float *p_m1, *p_r1, *p_m2, *p_r2, *p_m3, *p_r3, *p_m4, *p_r4;
    cudaGetSymbolAddress((void**)&p_q,    g_q);
    cudaGetSymbolAddress((void**)&p_cq,   g_cq);
    cudaGetSymbolAddress((void**)&p_wac,  g_Wac);
    cudaGetSymbolAddress((void**)&p_ha,   g_hist_attn);
    cudaGetSymbolAddress((void**)&p_join, g_join);
    cudaGetSymbolAddress((void**)&p_y1,   g_y1);
    cudaGetSymbolAddress((void**)&p_y2,   g_y2);
    cudaGetSymbolAddress((void**)&p_m1,   g_m1);
    cudaGetSymbolAddress((void**)&p_r1,   g_r1);
    cudaGetSymbolAddress((void**)&p_m2,   g_m2);
    cudaGetSymbolAddress((void**)&p_r2,   g_r2);
    cudaGetSymbolAddress((void**)&p_m3,   g_m3);
    cudaGetSymbolAddress((void**)&p_r3,   g_r3);
    cudaGetSymbolAddress((void**)&p_m4,   g_m4);
    cudaGetSymbolAddress((void**)&p_r4,   g_r4);

    cudaFuncSetAttribute(att_kernel, cudaFuncAttributeMaxDynamicSharedMemorySize,
                         SMEM_ATT_TOTAL);

    auto smemG = [](int KIN, int JOUT) { return (JOUT + 18) * (KIN + 2) * 4; };
    cudaFuncSetAttribute((const void*)gemm_smemW<128, 80, 0>,
        cudaFuncAttributeMaxDynamicSharedMemorySize, smemG(128, 80));
    cudaFuncSetAttribute((const void*)gemm_smemW<128, 128, 1>,
        cudaFuncAttributeMaxDynamicSharedMemorySize, smemG(128, 128));
    cudaFuncSetAttribute((const void*)gemm_smemW<384, 80, 1>,
        cudaFuncAttributeMaxDynamicSharedMemorySize, smemG(384, 80));
    cudaFuncSetAttribute((const void*)gemm_smemW<80, 40, 2>,
        cudaFuncAttributeMaxDynamicSharedMemorySize, smemG(80, 40));

    // 1-3: prep (att lands in profile slot 4)
    fold_W<<<(KK * D1 + 255) / 256, 256>>>(att_W1, att_W2);
    prep_batch<<<BB, 128>>>(user, item, cate_list, user_table, item_table,
                            cate_table, item_bias);
    gemm_smemW<128, 80, 0><<<BB / 16, 256, smemG(128, 80)>>>(
        p_q, KK, p_wac, att_b1, p_cq, D1, 0, nullptr, nullptr, nullptr, nullptr);

    // 4: ATT (scores + fused softmax/bag; 3 CTAs/SM)
    att_kernel<<<2 * BB, 256, SMEM_ATT_TOTAL>>>(history, length, cate_list,
                                                item_table, cate_table,
                                                att_b2, att_W3, att_b3);

    // tail
    colstats2<<<(KK + 31) / 32, 512>>>(p_ha, BB, KK, p_m1, p_r1);
    gemm_smemW<128, 128, 1><<<BB / 16, 256, smemG(128, 128)>>>(
        p_ha, KK, hist_W, hist_b, p_join, DJ, 256, p_m1, p_r1, hbn_gamma, hbn_beta);
    colstats2<<<(DJ + 31) / 32, 512>>>(p_join, BB, DJ, p_m2, p_r2);
    gemm_smemW<384, 80, 1><<<BB / 16, 256, smemG(384, 80)>>>(
        p_join, DJ, fc1_W, fc1_b, p_y1, D1, 0, p_m2, p_r2, fbn_gamma, fbn_beta);
    colstats2<<<(D1 + 31) / 32, 512>>>(p_y1, BB, D1, p_m3, p_r3);
    gemm_smemW<80, 40, 2><<<BB / 16, 256, smemG(80, 40)>>>(
        p_y1, D1, fc2_W, fc2_b, p_y2, D2, 0, p_m3, p_r3, d1_alpha, d1_beta);
    colstats2<<<(D2 + 31) / 32, 512>>>(p_y2, BB, D2, p_m4, p_r4);
    final_k<<<(BB + 255) / 256, 256>>>(fc3_W, fc3_b, d2_alpha, d2_beta, out, out_size);
}